// round 13
// baseline (speedup 1.0000x reference)
#include <cuda_runtime.h>
#include <cuda_bf16.h>

// Problem constants (setup_inputs is fixed: T=262144, HID=32, time = arange(T))
#define MAX_T 262144

// Trajectory scratch: ys[t] = (s_snow, s_water). 2 MB.
__device__ float2 g_ys[MAX_T];
// Precomputed per-step forcing records: [2i] = {ph, tmh, ldh, gate_h},
// [2i+1] = {p1, tm1, ld1, gate_n}.  8 MB.
__device__ float4 g_fc[2 * MAX_T];

// ---------------- fast transcendentals ----------------
// .ftz is load-bearing: non-ftz approx ops get a denormal fixup sequence.
__device__ __forceinline__ float ex2f(float x) {
    float y; asm("ex2.approx.ftz.f32 %0, %1;" : "=f"(y) : "f"(x)); return y;
}
__device__ __forceinline__ float rcpf(float x) {
    float y; asm("rcp.approx.ftz.f32 %0, %1;" : "=f"(y) : "f"(x)); return y;
}
// tanh from PRE-SCALED argument zs = 2*log2(e)*z:  tanh(z) = 1 - 2/(2^zs + 1)
__device__ __forceinline__ float tanh_scaled(float zs) {
    float t = ex2f(zs);
    float r = rcpf(t + 1.0f);
    return fmaf(-2.0f, r, 1.0f);
}
// step_fn(x) = sigmoid(10x)
__device__ __forceinline__ float fast_step(float x) {
    float t = ex2f(x * -14.426950408889634f);   // e^{-10x}
    return rcpf(1.0f + t);
}

#define L2E  1.4426950408889634f
#define SCL  2.885390081777927f    // 2*log2(e)

// ---------------- packed f32x2 (Blackwell FFMA2; PTX-only) ---------------
typedef unsigned long long u64;
__device__ __forceinline__ u64 pack2(float lo, float hi) {
    u64 r; asm("mov.b64 %0, {%1, %2};" : "=l"(r) : "f"(lo), "f"(hi)); return r;
}
__device__ __forceinline__ void unpack2(u64 v, float& lo, float& hi) {
    asm("mov.b64 {%0, %1}, %2;" : "=f"(lo), "=f"(hi) : "l"(v));
}
__device__ __forceinline__ u64 fma2(u64 a, u64 b, u64 c) {
    u64 d; asm("fma.rn.f32x2 %0, %1, %2, %3;" : "=l"(d) : "l"(a), "l"(b), "l"(c));
    return d;
}
__device__ __forceinline__ u64 mul2(u64 a, u64 b) {
    u64 d; asm("mul.rn.f32x2 %0, %1, %2;" : "=l"(d) : "l"(a), "l"(b));
    return d;
}
__device__ __forceinline__ u64 add2(u64 a, u64 b) {
    u64 d; asm("add.rn.f32x2 %0, %1, %2;" : "=l"(d) : "l"(a), "l"(b));
    return d;
}
__device__ __forceinline__ void lds128_2u64(unsigned addr, u64& a, u64& b) {
    asm volatile("ld.shared.v2.u64 {%0, %1}, [%2];" : "=l"(a), "=l"(b) : "r"(addr));
}

// Packed 32-term dot: 8 LDS.128, then 8 INDEPENDENT 2-deep FMA2 chains
// (min dependency depth), 3-level add2 tree, unpack + add.
__device__ __forceinline__ float dot32_packed(unsigned hvaddr,
                                              const u64 (&wp)[16], u64 seed01)
{
    u64 h0, h1, h2, h3, h4, h5, h6, h7;
    u64 h8, h9, hA, hB, hC, hD, hE, hF;
    lds128_2u64(hvaddr +   0, h0, h1);
    lds128_2u64(hvaddr +  16, h2, h3);
    lds128_2u64(hvaddr +  32, h4, h5);
    lds128_2u64(hvaddr +  48, h6, h7);
    lds128_2u64(hvaddr +  64, h8, h9);
    lds128_2u64(hvaddr +  80, hA, hB);
    lds128_2u64(hvaddr +  96, hC, hD);
    lds128_2u64(hvaddr + 112, hE, hF);
    u64 a0 = fma2(h0, wp[0], seed01);
    u64 a1 = mul2(h1, wp[1]);
    u64 a2 = mul2(h2, wp[2]);
    u64 a3 = mul2(h3, wp[3]);
    u64 a4 = mul2(h4, wp[4]);
    u64 a5 = mul2(h5, wp[5]);
    u64 a6 = mul2(h6, wp[6]);
    u64 a7 = mul2(h7, wp[7]);
    a0 = fma2(h8, wp[8],  a0);
    a1 = fma2(h9, wp[9],  a1);
    a2 = fma2(hA, wp[10], a2);
    a3 = fma2(hB, wp[11], a3);
    a4 = fma2(hC, wp[12], a4);
    a5 = fma2(hD, wp[13], a5);
    a6 = fma2(hE, wp[14], a6);
    a7 = fma2(hF, wp[15], a7);
    u64 s = add2(add2(add2(a0, a1), add2(a2, a3)),
                 add2(add2(a4, a5), add2(a6, a7)));
    float x, y;
    unpack2(s, x, y);
    return x + y;
}

// One RHS evaluation, PRE-SCALED pipeline (see R12).  The gate chain
// (fast_step + mult selects) is computed INSIDE, after the h1 exchange,
// so its MUFUs/selects issue in the layer-2 dot's shadow instead of
// delaying the critical-path tanh at stage entry.
//   mA  = (c==0) ? 0.5*gate_stage : 0.5      (hoisted per-step, off-path)
//   mld = stage's lday value
__device__ __forceinline__ void rhs_eval(
    int c, int j, float zsc, float s0p, float s1p, float mA, float mld,
    const u64 (&w2p)[16], u64 b2seed,
    const u64 (&w3p)[16], u64 b3seed,
    float* __restrict__ sh1, unsigned sh1a,
    float* __restrict__ sh2, unsigned sh2a,
    float& u0, float& u1, float& u2, float& u3, float& u4)
{
    const unsigned FULL = 0xffffffffu;

    float h1 = tanh_scaled(zsc);
    sh1[j] = h1;
    __syncthreads();

    // gate chain in the dot shadow (MUFU pipe idle here)
    float st = fast_step((c == 2) ? s0p : s1p);
    float mB = (c == 2) ? 0.5f * st : st * mld;
    float mult = (c < 2) ? mA : ((c < 4) ? mB : st);

    float zsc2 = dot32_packed(sh1a, w2p, b2seed);   // 2*log2e-scaled
    float h2 = tanh_scaled(zsc2);
    sh2[j] = h2;
    __syncthreads();

    float ko = dot32_packed(sh2a, w3p, b3seed);     // log2e-scaled

    float ep = ex2f(ko);                 // e^{o_c}
    float en = ex2f(-ko);                // e^{-o_c}
    float shm = fmaxf(ep - en, 0.0f);    // 2*relu(sinh); 0.5 folded into mult
    float f = (c < 3) ? shm : ep;
    float val = mult * f;

    u0 = __shfl_sync(FULL, val, 0);
    u1 = __shfl_sync(FULL, val, 1);
    u2 = __shfl_sync(FULL, val, 2);
    u3 = __shfl_sync(FULL, val, 3);
    u4 = __shfl_sync(FULL, val, 4);
}

// zsc = base + c0*(u0-u2) + c1*(u1+u2-u3-u4), 3-level FMA tree (scaled).
__device__ __forceinline__ float zfromu(float u0, float u1, float u2,
                                        float u3, float u4, float base,
                                        float c0, float c1, float c2, float nc1)
{
    float t1  = fmaf(c0, u0, base);
    float t2  = c1 * u1;
    float u34 = u3 + u4;
    float t3  = fmaf(c2, u2, t1);
    float t4  = fmaf(nc1, u34, t2);
    return t3 + t4;
}

// Forcing precompute: fully parallel.
__global__ void forcing_kernel(const float* __restrict__ inputs,
                               const float* __restrict__ lday, int T)
{
    int i = blockIdx.x * blockDim.x + threadIdx.x;
    if (i >= T) return;
    int i1 = (i + 1 < T) ? i + 1 : T - 1;
    float p0  = inputs[(size_t)i  * 5 + 2];
    float tm0 = inputs[(size_t)i  * 5 + 3];
    float ld0 = lday[i];
    float p1  = inputs[(size_t)i1 * 5 + 2];
    float tm1 = inputs[(size_t)i1 * 5 + 3];
    float ld1 = lday[i1];
    float ph = 0.5f * (p0 + p1), tmh = 0.5f * (tm0 + tm1), ldh = 0.5f * (ld0 + ld1);
    g_fc[2 * i]     = make_float4(ph, tmh, ldh, fast_step(-tmh));
    g_fc[2 * i + 1] = make_float4(p1, tm1, ld1, fast_step(-tm1));
}

// Sequential RK4 scan: ONE warp, latency-optimized.
__global__ void __launch_bounds__(32, 1)
scan_kernel(const float* __restrict__ inputs,
            const float* __restrict__ lday,
            const float* __restrict__ W1,
            const float* __restrict__ b1,
            const float* __restrict__ W2,
            const float* __restrict__ b2,
            const float* __restrict__ W3,
            const float* __restrict__ b3,
            int T)
{
    __shared__ __align__(16) float shA1[32], shA2[32];
    __shared__ __align__(16) float shB1[32], shB2[32];

    const int j = threadIdx.x;
    const int c = j % 5;

    const unsigned shA1a = (unsigned)__cvta_generic_to_shared(shA1);
    const unsigned shA2a = (unsigned)__cvta_generic_to_shared(shA2);
    const unsigned shB1a = (unsigned)__cvta_generic_to_shared(shB1);
    const unsigned shB2a = (unsigned)__cvta_generic_to_shared(shB2);

    // ---- layer-1 weights, PRE-SCALED by 2*log2e ----
    const float w10s = SCL * W1[0 * 32 + j];
    const float w11s = SCL * W1[1 * 32 + j];
    const float w12s = SCL * W1[2 * 32 + j];
    const float w13s = SCL * W1[3 * 32 + j];
    const float b1js = SCL * b1[j];

    // layer-2 packed weights, PRE-SCALED by 2*log2e
    u64 w2p[16];
#pragma unroll
    for (int k = 0; k < 16; k++)
        w2p[k] = pack2(SCL * W2[(2 * k) * 32 + j], SCL * W2[(2 * k + 1) * 32 + j]);
    const u64 b2seed = pack2(SCL * b2[j], 0.0f);

    // layer-3 packed weights, PRE-SCALED by log2e
    u64 w3p[16];
#pragma unroll
    for (int k = 0; k < 16; k++)
        w3p[k] = pack2(L2E * W3[(2 * k) * 5 + c], L2E * W3[(2 * k + 1) * 5 + c]);
    const u64 b3seed = pack2(L2E * b3[c], 0.0f);

    // hop-coefficient sets (scaled): half (k2,k3), full (k4)
    const float ch0 = 0.5f * w10s, ch1 = 0.5f * w11s;
    const float ch2 = ch1 - ch0, nch1 = -ch1;
    const float cf0 = w10s, cf1 = w11s, cf2 = cf1 - cf0, ncf1 = -cf1;

    // ---- initial state ----
    float s0 = inputs[0];
    float s1 = inputs[1];
    if (j == 0) g_ys[0] = make_float2(s0, s1);

    float p0  = inputs[2];
    float tm0 = inputs[3];
    float ld0 = lday[0];
    float a1is   = fmaf(tm0, w13s, fmaf(p0, w12s, b1js));
    float gate_i = fast_step(-tm0);
    float zss    = fmaf(s1, w11s, s0 * w10s);
    float z1s    = a1is + zss;

    float4 fa = g_fc[0];
    float4 fb = g_fc[1];

    const int steps = T - 1;
#pragma unroll 1
    for (int i = 0; i < steps; i++) {
        float4 faN = __ldg(&g_fc[2 * i + 2]);
        float4 fbN = __ldg(&g_fc[2 * i + 3]);

        float ldh = fa.z, gate_h = fa.w;
        float ld1 = fb.z, gate_n = fb.w;

        float a1hs   = fmaf(fa.y, w13s, fmaf(fa.x, w12s, b1js));
        float a1ns   = fmaf(fb.y, w13s, fmaf(fb.x, w12s, b1js));
        float base_h = a1hs + zss;
        float base_n = a1ns + zss;

        // per-step hoisted gate selects (off-path; only lane c==0 differs)
        float mA_i = (c == 0) ? 0.5f * gate_i : 0.5f;
        float mA_h = (c == 0) ? 0.5f * gate_h : 0.5f;
        float mA_n = (c == 0) ? 0.5f * gate_n : 0.5f;

        float u0, u1, u2, u3, u4;
        float k1_0, k1_1, k2_0, k2_1, k3_0, k3_1;

        // ---- stage 1 ----
        rhs_eval(c, j, z1s, s0, s1, mA_i, ld0, w2p, b2seed, w3p, b3seed,
                 shA1, shA1a, shA2, shA2a, u0, u1, u2, u3, u4);
        float z2s = zfromu(u0, u1, u2, u3, u4, base_h, ch0, ch1, ch2, nch1);
        k1_0 = u0 - u2; k1_1 = (u1 + u2) - (u3 + u4);

        // ---- stage 2 ----
        {
            float s0p = fmaf(0.5f, k1_0, s0), s1p = fmaf(0.5f, k1_1, s1);
            rhs_eval(c, j, z2s, s0p, s1p, mA_h, ldh, w2p, b2seed, w3p, b3seed,
                     shB1, shB1a, shB2, shB2a, u0, u1, u2, u3, u4);
        }
        float z3s = zfromu(u0, u1, u2, u3, u4, base_h, ch0, ch1, ch2, nch1);
        k2_0 = u0 - u2; k2_1 = (u1 + u2) - (u3 + u4);

        // ---- stage 3 ----
        {
            float s0p = fmaf(0.5f, k2_0, s0), s1p = fmaf(0.5f, k2_1, s1);
            rhs_eval(c, j, z3s, s0p, s1p, mA_h, ldh, w2p, b2seed, w3p, b3seed,
                     shA1, shA1a, shA2, shA2a, u0, u1, u2, u3, u4);
        }
        float z4s = zfromu(u0, u1, u2, u3, u4, base_n, cf0, cf1, cf2, ncf1);
        k3_0 = u0 - u2; k3_1 = (u1 + u2) - (u3 + u4);

        // ---- stage 4 ----
        {
            float s0p = s0 + k3_0, s1p = s1 + k3_1;
            rhs_eval(c, j, z4s, s0p, s1p, mA_n, ld1, w2p, b2seed, w3p, b3seed,
                     shB1, shB1a, shB2, shB2a, u0, u1, u2, u3, u4);
        }
        float acc0 = k1_0 + 2.0f * (k2_0 + k3_0);
        float acc1 = k1_1 + 2.0f * (k2_1 + k3_1);
        float k4_0 = u0 - u2, k4_1 = (u1 + u2) - (u3 + u4);

        // state update, z1 RE-ANCHORED to s (no independent z drift):
        s0 = fmaf(1.0f / 6.0f, acc0 + k4_0, s0);
        s1 = fmaf(1.0f / 6.0f, acc1 + k4_1, s1);
        zss = fmaf(s1, w11s, s0 * w10s);
        z1s = a1ns + zss;

        if (j == 0) g_ys[i + 1] = make_float2(s0, s1);

        // rolls
        a1is = a1ns; gate_i = gate_n; ld0 = ld1;
        fa = faN; fb = fbN;
    }
}

// Parallel final MLP over the trajectory: out[t] = mlp(x_t)[4].
__global__ void final_mlp_kernel(const float* __restrict__ inputs,
                                 const float* __restrict__ W1,
                                 const float* __restrict__ b1,
                                 const float* __restrict__ W2,
                                 const float* __restrict__ b2,
                                 const float* __restrict__ W3,
                                 const float* __restrict__ b3,
                                 float* __restrict__ out,
                                 int T)
{
    __shared__ float sW1[128];
    __shared__ float sb1[32];
    __shared__ float sW2[1024];
    __shared__ float sb2[32];
    __shared__ float sW3c[32];

    const int tid = threadIdx.x;
    for (int i = tid; i < 128;  i += blockDim.x) sW1[i] = W1[i];
    for (int i = tid; i < 32;   i += blockDim.x) sb1[i] = b1[i];
    for (int i = tid; i < 1024; i += blockDim.x) sW2[i] = W2[i];
    for (int i = tid; i < 32;   i += blockDim.x) sb2[i] = b2[i];
    for (int i = tid; i < 32;   i += blockDim.x) sW3c[i] = W3[i * 5 + 4];
    __syncthreads();

    const int t = blockIdx.x * blockDim.x + tid;
    if (t >= T) return;

    float2 y = g_ys[t];
    float s0 = fmaxf(y.x, 0.0f);
    float s1 = fmaxf(y.y, 0.0f);
    const float* row = inputs + (size_t)t * 5;
    float p  = row[2];
    float tm = row[3];

    float h1[32];
#pragma unroll
    for (int k = 0; k < 32; k++) {
        float z = sb1[k];
        z = fmaf(s0, sW1[0 * 32 + k], z);
        z = fmaf(s1, sW1[1 * 32 + k], z);
        z = fmaf(p,  sW1[2 * 32 + k], z);
        z = fmaf(tm, sW1[3 * 32 + k], z);
        h1[k] = tanh_scaled(z * SCL);
    }

    float acc = b3[4];
#pragma unroll
    for (int jj = 0; jj < 32; jj++) {
        float a = sb2[jj];
#pragma unroll
        for (int k = 0; k < 32; k++) {
            a = fmaf(h1[k], sW2[k * 32 + jj], a);
        }
        acc = fmaf(tanh_scaled(a * SCL), sW3c[jj], acc);
    }
    out[t] = acc;
}

extern "C" void kernel_launch(void* const* d_in, const int* in_sizes, int n_in,
                              void* d_out, int out_size)
{
    const float* inputs = (const float*)d_in[0];
    const float* lday   = (const float*)d_in[1];
    const float* W1     = (const float*)d_in[2];
    const float* b1     = (const float*)d_in[3];
    const float* W2     = (const float*)d_in[4];
    const float* b2     = (const float*)d_in[5];
    const float* W3     = (const float*)d_in[6];
    const float* b3     = (const float*)d_in[7];

    const int T = in_sizes[1];   // lday has T elements

    forcing_kernel<<<(T + 255) / 256, 256>>>(inputs, lday, T);
    scan_kernel<<<1, 32>>>(inputs, lday, W1, b1, W2, b2, W3, b3, T);

    const int threads = 256;
    const int blocks  = (T + threads - 1) / threads;
    final_mlp_kernel<<<blocks, threads>>>(inputs, W1, b1, W2, b2, W3, b3,
                                          (float*)d_out, T);
}

// round 14
// speedup vs baseline: 1.0604x; 1.0604x over previous
#include <cuda_runtime.h>
#include <cuda_bf16.h>

// Problem constants (setup_inputs is fixed: T=262144, HID=32, time = arange(T))
#define MAX_T 262144

// Trajectory scratch: ys[t] = (s_snow, s_water). 2 MB.
__device__ float2 g_ys[MAX_T];
// Precomputed per-step forcing records: [2i] = {ph, tmh, ldh, gate_h},
// [2i+1] = {p1, tm1, ld1, gate_n}.  8 MB.
__device__ float4 g_fc[2 * MAX_T];

// ---------------- fast transcendentals ----------------
// .ftz is load-bearing: non-ftz approx ops get a denormal fixup sequence.
__device__ __forceinline__ float ex2f(float x) {
    float y; asm("ex2.approx.ftz.f32 %0, %1;" : "=f"(y) : "f"(x)); return y;
}
__device__ __forceinline__ float rcpf(float x) {
    float y; asm("rcp.approx.ftz.f32 %0, %1;" : "=f"(y) : "f"(x)); return y;
}
// tanh from PRE-SCALED argument zs = 2*log2(e)*z (final_mlp only)
__device__ __forceinline__ float tanh_scaled(float zs) {
    float t = ex2f(zs);
    float r = rcpf(t + 1.0f);
    return fmaf(-2.0f, r, 1.0f);
}
// "r-form" of tanh: tanh(z) = 1 - 2*rform(zsc).  The affine (1,-2) part is
// folded into the NEXT layer's weights, so only r goes to smem.
__device__ __forceinline__ float tanh_rform(float zsc) {
    float t = ex2f(zsc);
    return rcpf(t + 1.0f);
}
// step_fn(x) = sigmoid(10x)
__device__ __forceinline__ float fast_step(float x) {
    float t = ex2f(x * -14.426950408889634f);   // e^{-10x}
    return rcpf(1.0f + t);
}

#define L2E  1.4426950408889634f
#define SCL  2.885390081777927f    // 2*log2(e)

// ---------------- packed f32x2 (Blackwell FFMA2; PTX-only) ---------------
typedef unsigned long long u64;
__device__ __forceinline__ u64 pack2(float lo, float hi) {
    u64 r; asm("mov.b64 %0, {%1, %2};" : "=l"(r) : "f"(lo), "f"(hi)); return r;
}
__device__ __forceinline__ void unpack2(u64 v, float& lo, float& hi) {
    asm("mov.b64 {%0, %1}, %2;" : "=f"(lo), "=f"(hi) : "l"(v));
}
__device__ __forceinline__ u64 fma2(u64 a, u64 b, u64 c) {
    u64 d; asm("fma.rn.f32x2 %0, %1, %2, %3;" : "=l"(d) : "l"(a), "l"(b), "l"(c));
    return d;
}
__device__ __forceinline__ u64 mul2(u64 a, u64 b) {
    u64 d; asm("mul.rn.f32x2 %0, %1, %2;" : "=l"(d) : "l"(a), "l"(b));
    return d;
}
__device__ __forceinline__ u64 add2(u64 a, u64 b) {
    u64 d; asm("add.rn.f32x2 %0, %1, %2;" : "=l"(d) : "l"(a), "l"(b));
    return d;
}
__device__ __forceinline__ void lds128_2u64(unsigned addr, u64& a, u64& b) {
    asm volatile("ld.shared.v2.u64 {%0, %1}, [%2];" : "=l"(a), "=l"(b) : "r"(addr));
}

// Packed 32-term dot (R12 layout: 4 accumulators, 4-deep FMA2 chains).
__device__ __forceinline__ float dot32_packed(unsigned hvaddr,
                                              const u64 (&wp)[16], u64 seed01)
{
    u64 h0, h1, h2, h3, h4, h5, h6, h7;
    u64 h8, h9, hA, hB, hC, hD, hE, hF;
    lds128_2u64(hvaddr +   0, h0, h1);
    lds128_2u64(hvaddr +  16, h2, h3);
    lds128_2u64(hvaddr +  32, h4, h5);
    lds128_2u64(hvaddr +  48, h6, h7);
    lds128_2u64(hvaddr +  64, h8, h9);
    lds128_2u64(hvaddr +  80, hA, hB);
    lds128_2u64(hvaddr +  96, hC, hD);
    lds128_2u64(hvaddr + 112, hE, hF);
    u64 a0 = fma2(h0, wp[0], seed01);
    u64 a1 = mul2(h1, wp[1]);
    u64 a2 = mul2(h2, wp[2]);
    u64 a3 = mul2(h3, wp[3]);
    a0 = fma2(h4, wp[4], a0);
    a1 = fma2(h5, wp[5], a1);
    a2 = fma2(h6, wp[6], a2);
    a3 = fma2(h7, wp[7], a3);
    a0 = fma2(h8, wp[8],  a0);
    a1 = fma2(h9, wp[9],  a1);
    a2 = fma2(hA, wp[10], a2);
    a3 = fma2(hB, wp[11], a3);
    a0 = fma2(hC, wp[12], a0);
    a1 = fma2(hD, wp[13], a1);
    a2 = fma2(hE, wp[14], a2);
    a3 = fma2(hF, wp[15], a3);
    u64 s = add2(add2(a0, a1), add2(a2, a3));
    float x, y;
    unpack2(s, x, y);
    return x + y;
}

// One RHS evaluation, PRE-SCALED + R-FOLDED pipeline:
//   layer-1: r1 = rform(zsc); smem <- r1  (affine folded into W2'/b2')
//   layer-2: zsc2 = dot(r1, W2') ; r2 = rform(zsc2); smem <- r2
//   layer-3: ko = dot(r2, W3')            (emits log2e-scaled output)
// mult precomputed by caller (R12 placement).
__device__ __forceinline__ void rhs_eval(
    int c, int j, float zsc, float mult,
    const u64 (&w2p)[16], u64 b2seed,
    const u64 (&w3p)[16], u64 b3seed,
    float* __restrict__ sh1, unsigned sh1a,
    float* __restrict__ sh2, unsigned sh2a,
    float& u0, float& u1, float& u2, float& u3, float& u4)
{
    const unsigned FULL = 0xffffffffu;

    float r1 = tanh_rform(zsc);
    sh1[j] = r1;
    __syncthreads();

    float zsc2 = dot32_packed(sh1a, w2p, b2seed);   // 2*log2e-scaled
    float r2 = tanh_rform(zsc2);
    sh2[j] = r2;
    __syncthreads();

    float ko = dot32_packed(sh2a, w3p, b3seed);     // log2e-scaled

    float ep = ex2f(ko);                 // e^{o_c}
    float en = ex2f(-ko);                // e^{-o_c}
    float shm = fmaxf(ep - en, 0.0f);    // 2*relu(sinh); 0.5 folded into mult
    float f = (c < 3) ? shm : ep;
    float val = mult * f;

    u0 = __shfl_sync(FULL, val, 0);
    u1 = __shfl_sync(FULL, val, 1);
    u2 = __shfl_sync(FULL, val, 2);
    u3 = __shfl_sync(FULL, val, 3);
    u4 = __shfl_sync(FULL, val, 4);
}

// zsc = base + c0*(u0-u2) + c1*(u1+u2-u3-u4), 3-level FMA tree (scaled).
__device__ __forceinline__ float zfromu(float u0, float u1, float u2,
                                        float u3, float u4, float base,
                                        float c0, float c1, float c2, float nc1)
{
    float t1  = fmaf(c0, u0, base);
    float t2  = c1 * u1;
    float u34 = u3 + u4;
    float t3  = fmaf(c2, u2, t1);
    float t4  = fmaf(nc1, u34, t2);
    return t3 + t4;
}

// Forcing precompute: fully parallel.
__global__ void forcing_kernel(const float* __restrict__ inputs,
                               const float* __restrict__ lday, int T)
{
    int i = blockIdx.x * blockDim.x + threadIdx.x;
    if (i >= T) return;
    int i1 = (i + 1 < T) ? i + 1 : T - 1;
    float p0  = inputs[(size_t)i  * 5 + 2];
    float tm0 = inputs[(size_t)i  * 5 + 3];
    float ld0 = lday[i];
    float p1  = inputs[(size_t)i1 * 5 + 2];
    float tm1 = inputs[(size_t)i1 * 5 + 3];
    float ld1 = lday[i1];
    float ph = 0.5f * (p0 + p1), tmh = 0.5f * (tm0 + tm1), ldh = 0.5f * (ld0 + ld1);
    g_fc[2 * i]     = make_float4(ph, tmh, ldh, fast_step(-tmh));
    g_fc[2 * i + 1] = make_float4(p1, tm1, ld1, fast_step(-tm1));
}

// Sequential RK4 scan: ONE warp, latency-optimized.
__global__ void __launch_bounds__(32, 1)
scan_kernel(const float* __restrict__ inputs,
            const float* __restrict__ lday,
            const float* __restrict__ W1,
            const float* __restrict__ b1,
            const float* __restrict__ W2,
            const float* __restrict__ b2,
            const float* __restrict__ W3,
            const float* __restrict__ b3,
            int T)
{
    __shared__ __align__(16) float shA1[32], shA2[32];
    __shared__ __align__(16) float shB1[32], shB2[32];

    const int j = threadIdx.x;
    const int c = j % 5;

    const unsigned shA1a = (unsigned)__cvta_generic_to_shared(shA1);
    const unsigned shA2a = (unsigned)__cvta_generic_to_shared(shA2);
    const unsigned shB1a = (unsigned)__cvta_generic_to_shared(shB1);
    const unsigned shB2a = (unsigned)__cvta_generic_to_shared(shB2);

    // ---- layer-1 weights, PRE-SCALED by 2*log2e ----
    const float w10s = SCL * W1[0 * 32 + j];
    const float w11s = SCL * W1[1 * 32 + j];
    const float w12s = SCL * W1[2 * 32 + j];
    const float w13s = SCL * W1[3 * 32 + j];
    const float b1js = SCL * b1[j];

    // layer-2: r-folded.  zsc2 = SCL*(b2 + SUM W2) + SUM (-2*SCL*W2)*r
    u64 w2p[16];
    float w2sum = 0.0f;
#pragma unroll
    for (int k = 0; k < 16; k++) {
        float lo = W2[(2 * k) * 32 + j];
        float hi = W2[(2 * k + 1) * 32 + j];
        w2sum += lo + hi;
        w2p[k] = pack2(-2.0f * SCL * lo, -2.0f * SCL * hi);
    }
    const u64 b2seed = pack2(SCL * (b2[j] + w2sum), 0.0f);

    // layer-3: r-folded.  ko = L2E*(b3 + SUM W3) + SUM (-2*L2E*W3)*r
    u64 w3p[16];
    float w3sum = 0.0f;
#pragma unroll
    for (int k = 0; k < 16; k++) {
        float lo = W3[(2 * k) * 5 + c];
        float hi = W3[(2 * k + 1) * 5 + c];
        w3sum += lo + hi;
        w3p[k] = pack2(-2.0f * L2E * lo, -2.0f * L2E * hi);
    }
    const u64 b3seed = pack2(L2E * (b3[c] + w3sum), 0.0f);

    // hop-coefficient sets (scaled): half (k2,k3), full (k4)
    const float ch0 = 0.5f * w10s, ch1 = 0.5f * w11s;
    const float ch2 = ch1 - ch0, nch1 = -ch1;
    const float cf0 = w10s, cf1 = w11s, cf2 = cf1 - cf0, ncf1 = -cf1;

    // ---- initial state ----
    float s0 = inputs[0];
    float s1 = inputs[1];
    if (j == 0) g_ys[0] = make_float2(s0, s1);

    float p0  = inputs[2];
    float tm0 = inputs[3];
    float ld0 = lday[0];
    float a1is   = fmaf(tm0, w13s, fmaf(p0, w12s, b1js));
    float gate_i = fast_step(-tm0);
    float zss    = fmaf(s1, w11s, s0 * w10s);
    float z1s    = a1is + zss;

    float4 fa = g_fc[0];
    float4 fb = g_fc[1];

    const int steps = T - 1;
#pragma unroll 1
    for (int i = 0; i < steps; i++) {
        float4 faN = __ldg(&g_fc[2 * i + 2]);
        float4 fbN = __ldg(&g_fc[2 * i + 3]);

        float ldh = fa.z, gate_h = fa.w;
        float ld1 = fb.z, gate_n = fb.w;

        float a1hs   = fmaf(fa.y, w13s, fmaf(fa.x, w12s, b1js));
        float a1ns   = fmaf(fb.y, w13s, fmaf(fb.x, w12s, b1js));
        float base_h = a1hs + zss;
        float base_n = a1ns + zss;

        float u0, u1, u2, u3, u4;
        float k1_0, k1_1, k2_0, k2_1, k3_0, k3_1;

        // ---- stage 1 ----
        {
            float st = fast_step((c == 2) ? s0 : s1);
            float mA = (c == 0) ? 0.5f * gate_i : 0.5f;
            float mB = (c == 2) ? 0.5f * st : st * ld0;
            float mult = (c < 2) ? mA : ((c < 4) ? mB : st);
            rhs_eval(c, j, z1s, mult, w2p, b2seed, w3p, b3seed,
                     shA1, shA1a, shA2, shA2a, u0, u1, u2, u3, u4);
        }
        float z2s = zfromu(u0, u1, u2, u3, u4, base_h, ch0, ch1, ch2, nch1);
        k1_0 = u0 - u2; k1_1 = (u1 + u2) - (u3 + u4);

        // ---- stage 2 ----
        {
            float s0p = fmaf(0.5f, k1_0, s0), s1p = fmaf(0.5f, k1_1, s1);
            float st = fast_step((c == 2) ? s0p : s1p);
            float mA = (c == 0) ? 0.5f * gate_h : 0.5f;
            float mB = (c == 2) ? 0.5f * st : st * ldh;
            float mult = (c < 2) ? mA : ((c < 4) ? mB : st);
            rhs_eval(c, j, z2s, mult, w2p, b2seed, w3p, b3seed,
                     shB1, shB1a, shB2, shB2a, u0, u1, u2, u3, u4);
        }
        float z3s = zfromu(u0, u1, u2, u3, u4, base_h, ch0, ch1, ch2, nch1);
        k2_0 = u0 - u2; k2_1 = (u1 + u2) - (u3 + u4);

        // ---- stage 3 ----
        {
            float s0p = fmaf(0.5f, k2_0, s0), s1p = fmaf(0.5f, k2_1, s1);
            float st = fast_step((c == 2) ? s0p : s1p);
            float mA = (c == 0) ? 0.5f * gate_h : 0.5f;
            float mB = (c == 2) ? 0.5f * st : st * ldh;
            float mult = (c < 2) ? mA : ((c < 4) ? mB : st);
            rhs_eval(c, j, z3s, mult, w2p, b2seed, w3p, b3seed,
                     shA1, shA1a, shA2, shA2a, u0, u1, u2, u3, u4);
        }
        float z4s = zfromu(u0, u1, u2, u3, u4, base_n, cf0, cf1, cf2, ncf1);
        k3_0 = u0 - u2; k3_1 = (u1 + u2) - (u3 + u4);

        // ---- stage 4 ----
        {
            float s0p = s0 + k3_0, s1p = s1 + k3_1;
            float st = fast_step((c == 2) ? s0p : s1p);
            float mA = (c == 0) ? 0.5f * gate_n : 0.5f;
            float mB = (c == 2) ? 0.5f * st : st * ld1;
            float mult = (c < 2) ? mA : ((c < 4) ? mB : st);
            rhs_eval(c, j, z4s, mult, w2p, b2seed, w3p, b3seed,
                     shB1, shB1a, shB2, shB2a, u0, u1, u2, u3, u4);
        }
        float acc0 = k1_0 + 2.0f * (k2_0 + k3_0);
        float acc1 = k1_1 + 2.0f * (k2_1 + k3_1);
        float k4_0 = u0 - u2, k4_1 = (u1 + u2) - (u3 + u4);

        // state update, z1 RE-ANCHORED to s (no independent z drift):
        s0 = fmaf(1.0f / 6.0f, acc0 + k4_0, s0);
        s1 = fmaf(1.0f / 6.0f, acc1 + k4_1, s1);
        zss = fmaf(s1, w11s, s0 * w10s);
        z1s = a1ns + zss;

        if (j == 0) g_ys[i + 1] = make_float2(s0, s1);

        // rolls
        a1is = a1ns; gate_i = gate_n; ld0 = ld1;
        fa = faN; fb = fbN;
    }
}

// Parallel final MLP over the trajectory: out[t] = mlp(x_t)[4].
__global__ void final_mlp_kernel(const float* __restrict__ inputs,
                                 const float* __restrict__ W1,
                                 const float* __restrict__ b1,
                                 const float* __restrict__ W2,
                                 const float* __restrict__ b2,
                                 const float* __restrict__ W3,
                                 const float* __restrict__ b3,
                                 float* __restrict__ out,
                                 int T)
{
    __shared__ float sW1[128];
    __shared__ float sb1[32];
    __shared__ float sW2[1024];
    __shared__ float sb2[32];
    __shared__ float sW3c[32];

    const int tid = threadIdx.x;
    for (int i = tid; i < 128;  i += blockDim.x) sW1[i] = W1[i];
    for (int i = tid; i < 32;   i += blockDim.x) sb1[i] = b1[i];
    for (int i = tid; i < 1024; i += blockDim.x) sW2[i] = W2[i];
    for (int i = tid; i < 32;   i += blockDim.x) sb2[i] = b2[i];
    for (int i = tid; i < 32;   i += blockDim.x) sW3c[i] = W3[i * 5 + 4];
    __syncthreads();

    const int t = blockIdx.x * blockDim.x + tid;
    if (t >= T) return;

    float2 y = g_ys[t];
    float s0 = fmaxf(y.x, 0.0f);
    float s1 = fmaxf(y.y, 0.0f);
    const float* row = inputs + (size_t)t * 5;
    float p  = row[2];
    float tm = row[3];

    float h1[32];
#pragma unroll
    for (int k = 0; k < 32; k++) {
        float z = sb1[k];
        z = fmaf(s0, sW1[0 * 32 + k], z);
        z = fmaf(s1, sW1[1 * 32 + k], z);
        z = fmaf(p,  sW1[2 * 32 + k], z);
        z = fmaf(tm, sW1[3 * 32 + k], z);
        h1[k] = tanh_scaled(z * SCL);
    }

    float acc = b3[4];
#pragma unroll
    for (int jj = 0; jj < 32; jj++) {
        float a = sb2[jj];
#pragma unroll
        for (int k = 0; k < 32; k++) {
            a = fmaf(h1[k], sW2[k * 32 + jj], a);
        }
        acc = fmaf(tanh_scaled(a * SCL), sW3c[jj], acc);
    }
    out[t] = acc;
}

extern "C" void kernel_launch(void* const* d_in, const int* in_sizes, int n_in,
                              void* d_out, int out_size)
{
    const float* inputs = (const float*)d_in[0];
    const float* lday   = (const float*)d_in[1];
    const float* W1     = (const float*)d_in[2];
    const float* b1     = (const float*)d_in[3];
    const float* W2     = (const float*)d_in[4];
    const float* b2     = (const float*)d_in[5];
    const float* W3     = (const float*)d_in[6];
    const float* b3     = (const float*)d_in[7];

    const int T = in_sizes[1];   // lday has T elements

    forcing_kernel<<<(T + 255) / 256, 256>>>(inputs, lday, T);
    scan_kernel<<<1, 32>>>(inputs, lday, W1, b1, W2, b2, W3, b3, T);

    const int threads = 256;
    const int blocks  = (T + threads - 1) / threads;
    final_mlp_kernel<<<blocks, threads>>>(inputs, W1, b1, W2, b2, W3, b3,
                                          (float*)d_out, T);
}

// round 15
// speedup vs baseline: 1.1035x; 1.0407x over previous
#include <cuda_runtime.h>
#include <cuda_bf16.h>

// Problem constants (setup_inputs is fixed: T=262144, HID=32, time = arange(T))
#define MAX_T 262144

// Trajectory scratch: ys[t] = (s_snow, s_water). 2 MB.
__device__ float2 g_ys[MAX_T];
// Precomputed per-step forcing records: [2i] = {ph, tmh, ldh, gate_h},
// [2i+1] = {p1, tm1, ld1, gate_n}.  8 MB.
__device__ float4 g_fc[2 * MAX_T];

// ---------------- fast transcendentals ----------------
// .ftz is load-bearing: non-ftz approx ops get a denormal fixup sequence.
__device__ __forceinline__ float ex2f(float x) {
    float y; asm("ex2.approx.ftz.f32 %0, %1;" : "=f"(y) : "f"(x)); return y;
}
__device__ __forceinline__ float rcpf(float x) {
    float y; asm("rcp.approx.ftz.f32 %0, %1;" : "=f"(y) : "f"(x)); return y;
}
// tanh from PRE-SCALED argument zs = 2*log2(e)*z (final_mlp only)
__device__ __forceinline__ float tanh_scaled(float zs) {
    float t = ex2f(zs);
    float r = rcpf(t + 1.0f);
    return fmaf(-2.0f, r, 1.0f);
}
// "r-form" of tanh: tanh(z) = 1 - 2*rform(zsc).  The affine (1,-2) part is
// folded into the NEXT layer's weights, so only r goes to smem.
__device__ __forceinline__ float tanh_rform(float zsc) {
    float t = ex2f(zsc);
    return rcpf(t + 1.0f);
}
// step_fn(x) = sigmoid(10x)
__device__ __forceinline__ float fast_step(float x) {
    float t = ex2f(x * -14.426950408889634f);   // e^{-10x}
    return rcpf(1.0f + t);
}

#define L2E  1.4426950408889634f
#define SCL  2.885390081777927f    // 2*log2(e)

// ---------------- packed f32x2 (Blackwell FFMA2; PTX-only) ---------------
typedef unsigned long long u64;
__device__ __forceinline__ u64 pack2(float lo, float hi) {
    u64 r; asm("mov.b64 %0, {%1, %2};" : "=l"(r) : "f"(lo), "f"(hi)); return r;
}
__device__ __forceinline__ void unpack2(u64 v, float& lo, float& hi) {
    asm("mov.b64 {%0, %1}, %2;" : "=f"(lo), "=f"(hi) : "l"(v));
}
__device__ __forceinline__ u64 fma2(u64 a, u64 b, u64 c) {
    u64 d; asm("fma.rn.f32x2 %0, %1, %2, %3;" : "=l"(d) : "l"(a), "l"(b), "l"(c));
    return d;
}
__device__ __forceinline__ u64 mul2(u64 a, u64 b) {
    u64 d; asm("mul.rn.f32x2 %0, %1, %2;" : "=l"(d) : "l"(a), "l"(b));
    return d;
}
__device__ __forceinline__ u64 add2(u64 a, u64 b) {
    u64 d; asm("add.rn.f32x2 %0, %1, %2;" : "=l"(d) : "l"(a), "l"(b));
    return d;
}
__device__ __forceinline__ void lds128_2u64(unsigned addr, u64& a, u64& b) {
    asm volatile("ld.shared.v2.u64 {%0, %1}, [%2];" : "=l"(a), "=l"(b) : "r"(addr));
}

// Packed 32-term dot (R12 layout: 4 accumulators, 4-deep FMA2 chains).
__device__ __forceinline__ float dot32_packed(unsigned hvaddr,
                                              const u64 (&wp)[16], u64 seed01)
{
    u64 h0, h1, h2, h3, h4, h5, h6, h7;
    u64 h8, h9, hA, hB, hC, hD, hE, hF;
    lds128_2u64(hvaddr +   0, h0, h1);
    lds128_2u64(hvaddr +  16, h2, h3);
    lds128_2u64(hvaddr +  32, h4, h5);
    lds128_2u64(hvaddr +  48, h6, h7);
    lds128_2u64(hvaddr +  64, h8, h9);
    lds128_2u64(hvaddr +  80, hA, hB);
    lds128_2u64(hvaddr +  96, hC, hD);
    lds128_2u64(hvaddr + 112, hE, hF);
    u64 a0 = fma2(h0, wp[0], seed01);
    u64 a1 = mul2(h1, wp[1]);
    u64 a2 = mul2(h2, wp[2]);
    u64 a3 = mul2(h3, wp[3]);
    a0 = fma2(h4, wp[4], a0);
    a1 = fma2(h5, wp[5], a1);
    a2 = fma2(h6, wp[6], a2);
    a3 = fma2(h7, wp[7], a3);
    a0 = fma2(h8, wp[8],  a0);
    a1 = fma2(h9, wp[9],  a1);
    a2 = fma2(hA, wp[10], a2);
    a3 = fma2(hB, wp[11], a3);
    a0 = fma2(hC, wp[12], a0);
    a1 = fma2(hD, wp[13], a1);
    a2 = fma2(hE, wp[14], a2);
    a3 = fma2(hF, wp[15], a3);
    u64 s = add2(add2(a0, a1), add2(a2, a3));
    float x, y;
    unpack2(s, x, y);
    return x + y;
}

// One RHS evaluation, PRE-SCALED + R-FOLDED pipeline (R14), with a
// TWO-CLASS tail: ve = mult*ep feeds u3/u4 (gathered EARLY, they're the
// deepest zfromu inputs); vs = fmax(ve - mult*en, 0) feeds u0..u2
// (valid since mult >= 0 on every lane).  No select on the path.
__device__ __forceinline__ void rhs_eval(
    int c, int j, float zsc, float mult,
    const u64 (&w2p)[16], u64 b2seed,
    const u64 (&w3p)[16], u64 b3seed,
    float* __restrict__ sh1, unsigned sh1a,
    float* __restrict__ sh2, unsigned sh2a,
    float& u0, float& u1, float& u2, float& u3, float& u4)
{
    const unsigned FULL = 0xffffffffu;

    float r1 = tanh_rform(zsc);
    sh1[j] = r1;
    __syncthreads();

    float zsc2 = dot32_packed(sh1a, w2p, b2seed);   // 2*log2e-scaled
    float r2 = tanh_rform(zsc2);
    sh2[j] = r2;
    __syncthreads();

    float ko = dot32_packed(sh2a, w3p, b3seed);     // log2e-scaled

    float ep = ex2f(ko);                 // e^{o_c}
    float en = ex2f(-ko);                // e^{-o_c}
    float ve = mult * ep;                // lanes c>=3: final value (et, q)
    u3 = __shfl_sync(FULL, ve, 3);       // earliest-ready, deepest consumers
    u4 = __shfl_sync(FULL, ve, 4);
    float men = mult * en;
    float vs = fmaxf(ve - men, 0.0f);    // lanes c<3: mult*2*relu(sinh)
    u0 = __shfl_sync(FULL, vs, 0);
    u1 = __shfl_sync(FULL, vs, 1);
    u2 = __shfl_sync(FULL, vs, 2);
}

// zsc = base + c0*(u0-u2) + c1*(u1+u2-u3-u4), 3-level FMA tree (scaled).
// u34 computed first (u3/u4 arrive earliest from the split gather).
__device__ __forceinline__ float zfromu(float u0, float u1, float u2,
                                        float u3, float u4, float base,
                                        float c0, float c1, float c2, float nc1)
{
    float u34 = u3 + u4;
    float t2  = c1 * u1;
    float t4  = fmaf(nc1, u34, t2);
    float t1  = fmaf(c0, u0, base);
    float t3  = fmaf(c2, u2, t1);
    return t3 + t4;
}

// Forcing precompute: fully parallel.
__global__ void forcing_kernel(const float* __restrict__ inputs,
                               const float* __restrict__ lday, int T)
{
    int i = blockIdx.x * blockDim.x + threadIdx.x;
    if (i >= T) return;
    int i1 = (i + 1 < T) ? i + 1 : T - 1;
    float p0  = inputs[(size_t)i  * 5 + 2];
    float tm0 = inputs[(size_t)i  * 5 + 3];
    float ld0 = lday[i];
    float p1  = inputs[(size_t)i1 * 5 + 2];
    float tm1 = inputs[(size_t)i1 * 5 + 3];
    float ld1 = lday[i1];
    float ph = 0.5f * (p0 + p1), tmh = 0.5f * (tm0 + tm1), ldh = 0.5f * (ld0 + ld1);
    g_fc[2 * i]     = make_float4(ph, tmh, ldh, fast_step(-tmh));
    g_fc[2 * i + 1] = make_float4(p1, tm1, ld1, fast_step(-tm1));
}

// Sequential RK4 scan: ONE warp, latency-optimized.
__global__ void __launch_bounds__(32, 1)
scan_kernel(const float* __restrict__ inputs,
            const float* __restrict__ lday,
            const float* __restrict__ W1,
            const float* __restrict__ b1,
            const float* __restrict__ W2,
            const float* __restrict__ b2,
            const float* __restrict__ W3,
            const float* __restrict__ b3,
            int T)
{
    __shared__ __align__(16) float shA1[32], shA2[32];
    __shared__ __align__(16) float shB1[32], shB2[32];

    const int j = threadIdx.x;
    const int c = j % 5;

    const unsigned shA1a = (unsigned)__cvta_generic_to_shared(shA1);
    const unsigned shA2a = (unsigned)__cvta_generic_to_shared(shA2);
    const unsigned shB1a = (unsigned)__cvta_generic_to_shared(shB1);
    const unsigned shB2a = (unsigned)__cvta_generic_to_shared(shB2);

    // ---- layer-1 weights, PRE-SCALED by 2*log2e ----
    const float w10s = SCL * W1[0 * 32 + j];
    const float w11s = SCL * W1[1 * 32 + j];
    const float w12s = SCL * W1[2 * 32 + j];
    const float w13s = SCL * W1[3 * 32 + j];
    const float b1js = SCL * b1[j];

    // layer-2: r-folded.  zsc2 = SCL*(b2 + SUM W2) + SUM (-2*SCL*W2)*r
    u64 w2p[16];
    float w2sum = 0.0f;
#pragma unroll
    for (int k = 0; k < 16; k++) {
        float lo = W2[(2 * k) * 32 + j];
        float hi = W2[(2 * k + 1) * 32 + j];
        w2sum += lo + hi;
        w2p[k] = pack2(-2.0f * SCL * lo, -2.0f * SCL * hi);
    }
    const u64 b2seed = pack2(SCL * (b2[j] + w2sum), 0.0f);

    // layer-3: r-folded.  ko = L2E*(b3 + SUM W3) + SUM (-2*L2E*W3)*r
    u64 w3p[16];
    float w3sum = 0.0f;
#pragma unroll
    for (int k = 0; k < 16; k++) {
        float lo = W3[(2 * k) * 5 + c];
        float hi = W3[(2 * k + 1) * 5 + c];
        w3sum += lo + hi;
        w3p[k] = pack2(-2.0f * L2E * lo, -2.0f * L2E * hi);
    }
    const u64 b3seed = pack2(L2E * (b3[c] + w3sum), 0.0f);

    // hop-coefficient sets (scaled): half (k2,k3), full (k4), sixth (boundary)
    const float ch0 = 0.5f * w10s, ch1 = 0.5f * w11s;
    const float ch2 = ch1 - ch0, nch1 = -ch1;
    const float cf0 = w10s, cf1 = w11s, cf2 = cf1 - cf0, ncf1 = -cf1;
    const float cs0 = w10s * (1.0f / 6.0f), cs1 = w11s * (1.0f / 6.0f);
    const float cs2 = cs1 - cs0, ncs1 = -cs1;

    // ---- initial state ----
    float s0 = inputs[0];
    float s1 = inputs[1];
    if (j == 0) g_ys[0] = make_float2(s0, s1);

    float p0  = inputs[2];
    float tm0 = inputs[3];
    float ld0 = lday[0];
    float gate_i = fast_step(-tm0);
    float zss    = fmaf(s1, w11s, s0 * w10s);
    float z1s    = fmaf(tm0, w13s, fmaf(p0, w12s, b1js)) + zss;

    float4 fa = g_fc[0];
    float4 fb = g_fc[1];

    const int steps = T - 1;
#pragma unroll 1
    for (int i = 0; i < steps; i++) {
        float4 faN = __ldg(&g_fc[2 * i + 2]);
        float4 fbN = __ldg(&g_fc[2 * i + 3]);

        float ldh = fa.z, gate_h = fa.w;
        float ld1 = fb.z, gate_n = fb.w;

        float a1hs   = fmaf(fa.y, w13s, fmaf(fa.x, w12s, b1js));
        float a1ns   = fmaf(fb.y, w13s, fmaf(fb.x, w12s, b1js));
        float base_h = a1hs + zss;
        float base_n = a1ns + zss;

        float u0, u1, u2, u3, u4;
        float k1_0, k1_1, k2_0, k2_1, k3_0, k3_1;

        // ---- stage 1 ----
        {
            float st = fast_step((c == 2) ? s0 : s1);
            float mA = (c == 0) ? 0.5f * gate_i : 0.5f;
            float mB = (c == 2) ? 0.5f * st : st * ld0;
            float mult = (c < 2) ? mA : ((c < 4) ? mB : st);
            rhs_eval(c, j, z1s, mult, w2p, b2seed, w3p, b3seed,
                     shA1, shA1a, shA2, shA2a, u0, u1, u2, u3, u4);
        }
        float z2s = zfromu(u0, u1, u2, u3, u4, base_h, ch0, ch1, ch2, nch1);
        k1_0 = u0 - u2; k1_1 = (u1 + u2) - (u3 + u4);

        // ---- stage 2 ----
        {
            float s0p = fmaf(0.5f, k1_0, s0), s1p = fmaf(0.5f, k1_1, s1);
            float st = fast_step((c == 2) ? s0p : s1p);
            float mA = (c == 0) ? 0.5f * gate_h : 0.5f;
            float mB = (c == 2) ? 0.5f * st : st * ldh;
            float mult = (c < 2) ? mA : ((c < 4) ? mB : st);
            rhs_eval(c, j, z2s, mult, w2p, b2seed, w3p, b3seed,
                     shB1, shB1a, shB2, shB2a, u0, u1, u2, u3, u4);
        }
        float z3s = zfromu(u0, u1, u2, u3, u4, base_h, ch0, ch1, ch2, nch1);
        k2_0 = u0 - u2; k2_1 = (u1 + u2) - (u3 + u4);

        // ---- stage 3 ----
        {
            float s0p = fmaf(0.5f, k2_0, s0), s1p = fmaf(0.5f, k2_1, s1);
            float st = fast_step((c == 2) ? s0p : s1p);
            float mA = (c == 0) ? 0.5f * gate_h : 0.5f;
            float mB = (c == 2) ? 0.5f * st : st * ldh;
            float mult = (c < 2) ? mA : ((c < 4) ? mB : st);
            rhs_eval(c, j, z3s, mult, w2p, b2seed, w3p, b3seed,
                     shA1, shA1a, shA2, shA2a, u0, u1, u2, u3, u4);
        }
        float z4s = zfromu(u0, u1, u2, u3, u4, base_n, cf0, cf1, cf2, ncf1);
        k3_0 = u0 - u2; k3_1 = (u1 + u2) - (u3 + u4);

        // boundary pre-accumulation (off-path; overlaps stage 4's body):
        //   A = base_n + cs0*acc0 + cs1*acc1,  z1_next = zfromu(u4s, A, cs*)
        // Exact-math identical to a1n + w.s_new; NO feedback (s and zss are
        // still updated exactly below), so no R11-style drift.
        float acc0 = k1_0 + 2.0f * (k2_0 + k3_0);
        float acc1 = k1_1 + 2.0f * (k2_1 + k3_1);
        float A    = fmaf(cs1, acc1, fmaf(cs0, acc0, base_n));

        // ---- stage 4 ----
        {
            float s0p = s0 + k3_0, s1p = s1 + k3_1;
            float st = fast_step((c == 2) ? s0p : s1p);
            float mA = (c == 0) ? 0.5f * gate_n : 0.5f;
            float mB = (c == 2) ? 0.5f * st : st * ld1;
            float mult = (c < 2) ? mA : ((c < 4) ? mB : st);
            rhs_eval(c, j, z4s, mult, w2p, b2seed, w3p, b3seed,
                     shB1, shB1a, shB2, shB2a, u0, u1, u2, u3, u4);
        }
        // next step's layer-1 preactivation straight from stage-4 u's
        z1s = zfromu(u0, u1, u2, u3, u4, A, cs0, cs1, cs2, ncs1);

        float k4_0 = u0 - u2, k4_1 = (u1 + u2) - (u3 + u4);
        s0 = fmaf(1.0f / 6.0f, acc0 + k4_0, s0);
        s1 = fmaf(1.0f / 6.0f, acc1 + k4_1, s1);
        // zss RE-ANCHORED to exact s every step (consumed by next base_h/base_n)
        zss = fmaf(s1, w11s, s0 * w10s);

        if (j == 0) g_ys[i + 1] = make_float2(s0, s1);

        // rolls
        gate_i = gate_n; ld0 = ld1;
        fa = faN; fb = fbN;
    }
}

// Parallel final MLP over the trajectory: out[t] = mlp(x_t)[4].
__global__ void final_mlp_kernel(const float* __restrict__ inputs,
                                 const float* __restrict__ W1,
                                 const float* __restrict__ b1,
                                 const float* __restrict__ W2,
                                 const float* __restrict__ b2,
                                 const float* __restrict__ W3,
                                 const float* __restrict__ b3,
                                 float* __restrict__ out,
                                 int T)
{
    __shared__ float sW1[128];
    __shared__ float sb1[32];
    __shared__ float sW2[1024];
    __shared__ float sb2[32];
    __shared__ float sW3c[32];

    const int tid = threadIdx.x;
    for (int i = tid; i < 128;  i += blockDim.x) sW1[i] = W1[i];
    for (int i = tid; i < 32;   i += blockDim.x) sb1[i] = b1[i];
    for (int i = tid; i < 1024; i += blockDim.x) sW2[i] = W2[i];
    for (int i = tid; i < 32;   i += blockDim.x) sb2[i] = b2[i];
    for (int i = tid; i < 32;   i += blockDim.x) sW3c[i] = W3[i * 5 + 4];
    __syncthreads();

    const int t = blockIdx.x * blockDim.x + tid;
    if (t >= T) return;

    float2 y = g_ys[t];
    float s0 = fmaxf(y.x, 0.0f);
    float s1 = fmaxf(y.y, 0.0f);
    const float* row = inputs + (size_t)t * 5;
    float p  = row[2];
    float tm = row[3];

    float h1[32];
#pragma unroll
    for (int k = 0; k < 32; k++) {
        float z = sb1[k];
        z = fmaf(s0, sW1[0 * 32 + k], z);
        z = fmaf(s1, sW1[1 * 32 + k], z);
        z = fmaf(p,  sW1[2 * 32 + k], z);
        z = fmaf(tm, sW1[3 * 32 + k], z);
        h1[k] = tanh_scaled(z * SCL);
    }

    float acc = b3[4];
#pragma unroll
    for (int jj = 0; jj < 32; jj++) {
        float a = sb2[jj];
#pragma unroll
        for (int k = 0; k < 32; k++) {
            a = fmaf(h1[k], sW2[k * 32 + jj], a);
        }
        acc = fmaf(tanh_scaled(a * SCL), sW3c[jj], acc);
    }
    out[t] = acc;
}

extern "C" void kernel_launch(void* const* d_in, const int* in_sizes, int n_in,
                              void* d_out, int out_size)
{
    const float* inputs = (const float*)d_in[0];
    const float* lday   = (const float*)d_in[1];
    const float* W1     = (const float*)d_in[2];
    const float* b1     = (const float*)d_in[3];
    const float* W2     = (const float*)d_in[4];
    const float* b2     = (const float*)d_in[5];
    const float* W3     = (const float*)d_in[6];
    const float* b3     = (const float*)d_in[7];

    const int T = in_sizes[1];   // lday has T elements

    forcing_kernel<<<(T + 255) / 256, 256>>>(inputs, lday, T);
    scan_kernel<<<1, 32>>>(inputs, lday, W1, b1, W2, b2, W3, b3, T);

    const int threads = 256;
    const int blocks  = (T + threads - 1) / threads;
    final_mlp_kernel<<<blocks, threads>>>(inputs, W1, b1, W2, b2, W3, b3,
                                          (float*)d_out, T);
}

// round 16
// speedup vs baseline: 1.1164x; 1.0116x over previous
#include <cuda_runtime.h>
#include <cuda_bf16.h>

// Problem constants (setup_inputs is fixed: T=262144, HID=32, time = arange(T))
#define MAX_T 262144

// Trajectory scratch: ys[t] = (s_snow, s_water). 2 MB.
__device__ float2 g_ys[MAX_T];
// Precomputed per-step forcing records: [2i] = {ph, tmh, ldh, gate_h},
// [2i+1] = {p1, tm1, ld1, gate_n}.  8 MB.
__device__ float4 g_fc[2 * MAX_T];

// ---------------- fast transcendentals ----------------
__device__ __forceinline__ float ex2f(float x) {
    float y; asm("ex2.approx.ftz.f32 %0, %1;" : "=f"(y) : "f"(x)); return y;
}
__device__ __forceinline__ float rcpf(float x) {
    float y; asm("rcp.approx.ftz.f32 %0, %1;" : "=f"(y) : "f"(x)); return y;
}
// tanh from PRE-SCALED argument (final_mlp only)
__device__ __forceinline__ float tanh_scaled(float zs) {
    float t = ex2f(zs);
    float r = rcpf(t + 1.0f);
    return fmaf(-2.0f, r, 1.0f);
}
// "r-form" of tanh: tanh(z) = 1 - 2*rform(zsc); affine folded into next layer.
__device__ __forceinline__ float tanh_rform(float zsc) {
    float t = ex2f(zsc);
    return rcpf(t + 1.0f);
}
// step_fn(x) = sigmoid(10x)
__device__ __forceinline__ float fast_step(float x) {
    float t = ex2f(x * -14.426950408889634f);
    return rcpf(1.0f + t);
}

#define L2E  1.4426950408889634f
#define SCL  2.885390081777927f    // 2*log2(e)

// ---------------- packed f32x2 (Blackwell FFMA2; PTX-only) ---------------
typedef unsigned long long u64;
__device__ __forceinline__ u64 pack2(float lo, float hi) {
    u64 r; asm("mov.b64 %0, {%1, %2};" : "=l"(r) : "f"(lo), "f"(hi)); return r;
}
__device__ __forceinline__ void unpack2(u64 v, float& lo, float& hi) {
    asm("mov.b64 {%0, %1}, %2;" : "=f"(lo), "=f"(hi) : "l"(v));
}
__device__ __forceinline__ u64 fma2(u64 a, u64 b, u64 c) {
    u64 d; asm("fma.rn.f32x2 %0, %1, %2, %3;" : "=l"(d) : "l"(a), "l"(b), "l"(c));
    return d;
}
__device__ __forceinline__ u64 mul2(u64 a, u64 b) {
    u64 d; asm("mul.rn.f32x2 %0, %1, %2;" : "=l"(d) : "l"(a), "l"(b));
    return d;
}
__device__ __forceinline__ u64 add2(u64 a, u64 b) {
    u64 d; asm("add.rn.f32x2 %0, %1, %2;" : "=l"(d) : "l"(a), "l"(b));
    return d;
}
__device__ __forceinline__ void lds128_2u64(unsigned addr, u64& a, u64& b) {
    asm volatile("ld.shared.v2.u64 {%0, %1}, [%2];" : "=l"(a), "=l"(b) : "r"(addr));
}
// Pinned shared store (ordering anchor: compiler cannot sink it past the
// drain-filler code that follows it).
__device__ __forceinline__ void sts32(unsigned addr, float v) {
    asm volatile("st.shared.f32 [%0], %1;" :: "r"(addr), "f"(v) : "memory");
}

// Packed 32-term dot (4 accumulators, 4-deep FMA2 chains).
__device__ __forceinline__ float dot32_packed(unsigned hvaddr,
                                              const u64 (&wp)[16], u64 seed01)
{
    u64 h0, h1, h2, h3, h4, h5, h6, h7;
    u64 h8, h9, hA, hB, hC, hD, hE, hF;
    lds128_2u64(hvaddr +   0, h0, h1);
    lds128_2u64(hvaddr +  16, h2, h3);
    lds128_2u64(hvaddr +  32, h4, h5);
    lds128_2u64(hvaddr +  48, h6, h7);
    lds128_2u64(hvaddr +  64, h8, h9);
    lds128_2u64(hvaddr +  80, hA, hB);
    lds128_2u64(hvaddr +  96, hC, hD);
    lds128_2u64(hvaddr + 112, hE, hF);
    u64 a0 = fma2(h0, wp[0], seed01);
    u64 a1 = mul2(h1, wp[1]);
    u64 a2 = mul2(h2, wp[2]);
    u64 a3 = mul2(h3, wp[3]);
    a0 = fma2(h4, wp[4], a0);
    a1 = fma2(h5, wp[5], a1);
    a2 = fma2(h6, wp[6], a2);
    a3 = fma2(h7, wp[7], a3);
    a0 = fma2(h8, wp[8],  a0);
    a1 = fma2(h9, wp[9],  a1);
    a2 = fma2(hA, wp[10], a2);
    a3 = fma2(hB, wp[11], a3);
    a0 = fma2(hC, wp[12], a0);
    a1 = fma2(hD, wp[13], a1);
    a2 = fma2(hE, wp[14], a2);
    a3 = fma2(hF, wp[15], a3);
    u64 s = add2(add2(a0, a1), add2(a2, a3));
    float x, y;
    unpack2(s, x, y);
    return x + y;
}

// One RHS evaluation (pre-scaled + r-folded + two-class tail).
// DRAIN-FILLING: the gate chain (fast_step + selects) executes BETWEEN the
// r1 STS and the first BAR, so the barrier's STS-drain overlaps independent
// MUFU work instead of stalling the post-BAR LDS.
__device__ __forceinline__ void rhs_eval(
    int c, int j, float zsc, float s0p, float s1p, float mA, float mld,
    const u64 (&w2p)[16], u64 b2seed,
    const u64 (&w3p)[16], u64 b3seed,
    unsigned sh1a, unsigned sh2a,
    float& u0, float& u1, float& u2, float& u3, float& u4)
{
    const unsigned FULL = 0xffffffffu;

    float r1 = tanh_rform(zsc);
    sts32(sh1a + 4u * j, r1);

    // ---- drain filler #1: gate chain (independent of r1) ----
    float st = fast_step((c == 2) ? s0p : s1p);
    float mB = (c == 2) ? 0.5f * st : st * mld;
    float mult = (c < 2) ? mA : ((c < 4) ? mB : st);

    __syncthreads();

    float zsc2 = dot32_packed(sh1a, w2p, b2seed);   // 2*log2e-scaled
    float r2 = tanh_rform(zsc2);
    sts32(sh2a + 4u * j, r2);
    __syncthreads();

    float ko = dot32_packed(sh2a, w3p, b3seed);     // log2e-scaled

    // ---- tail: en first (men ready when ve lands) ----
    float en = ex2f(-ko);                // e^{-o_c}
    float ep = ex2f(ko);                 // e^{o_c}
    float men = mult * en;
    float ve  = mult * ep;               // lanes c>=3: final value (et, q)
    u3 = __shfl_sync(FULL, ve, 3);       // earliest-ready, deepest consumers
    u4 = __shfl_sync(FULL, ve, 4);
    float vs = fmaxf(ve - men, 0.0f);    // lanes c<3: mult*2*relu(sinh)
    u0 = __shfl_sync(FULL, vs, 0);
    u1 = __shfl_sync(FULL, vs, 1);
    u2 = __shfl_sync(FULL, vs, 2);
}

// zsc = base + c0*(u0-u2) + c1*(u1+u2-u3-u4).  Q0 = fmaf(nc1,u34,base)
// precomputed from early u3/u4; post-(u0,u1,u2) depth = 2 FMA + 1 add.
__device__ __forceinline__ float zfromu(float u0, float u1, float u2,
                                        float u3, float u4, float base,
                                        float c0, float c1, float c2, float nc1)
{
    float u34 = u3 + u4;
    float Q0  = fmaf(nc1, u34, base);
    float A   = fmaf(c0, u0, Q0);
    float B   = fmaf(c2, u2, c1 * u1);
    return A + B;
}

// Forcing precompute: fully parallel.
__global__ void forcing_kernel(const float* __restrict__ inputs,
                               const float* __restrict__ lday, int T)
{
    int i = blockIdx.x * blockDim.x + threadIdx.x;
    if (i >= T) return;
    int i1 = (i + 1 < T) ? i + 1 : T - 1;
    float p0  = inputs[(size_t)i  * 5 + 2];
    float tm0 = inputs[(size_t)i  * 5 + 3];
    float ld0 = lday[i];
    float p1  = inputs[(size_t)i1 * 5 + 2];
    float tm1 = inputs[(size_t)i1 * 5 + 3];
    float ld1 = lday[i1];
    float ph = 0.5f * (p0 + p1), tmh = 0.5f * (tm0 + tm1), ldh = 0.5f * (ld0 + ld1);
    g_fc[2 * i]     = make_float4(ph, tmh, ldh, fast_step(-tmh));
    g_fc[2 * i + 1] = make_float4(p1, tm1, ld1, fast_step(-tm1));
}

// Sequential RK4 scan: ONE warp, latency-optimized.
__global__ void __launch_bounds__(32, 1)
scan_kernel(const float* __restrict__ inputs,
            const float* __restrict__ lday,
            const float* __restrict__ W1,
            const float* __restrict__ b1,
            const float* __restrict__ W2,
            const float* __restrict__ b2,
            const float* __restrict__ W3,
            const float* __restrict__ b3,
            int T)
{
    __shared__ __align__(16) float shA1[32], shA2[32];
    __shared__ __align__(16) float shB1[32], shB2[32];

    const int j = threadIdx.x;
    const int c = j % 5;

    const unsigned shA1a = (unsigned)__cvta_generic_to_shared(shA1);
    const unsigned shA2a = (unsigned)__cvta_generic_to_shared(shA2);
    const unsigned shB1a = (unsigned)__cvta_generic_to_shared(shB1);
    const unsigned shB2a = (unsigned)__cvta_generic_to_shared(shB2);

    // ---- layer-1 weights, PRE-SCALED by 2*log2e ----
    const float w10s = SCL * W1[0 * 32 + j];
    const float w11s = SCL * W1[1 * 32 + j];
    const float w12s = SCL * W1[2 * 32 + j];
    const float w13s = SCL * W1[3 * 32 + j];
    const float b1js = SCL * b1[j];

    // layer-2: r-folded.  zsc2 = SCL*(b2 + SUM W2) + SUM (-2*SCL*W2)*r
    u64 w2p[16];
    float w2sum = 0.0f;
#pragma unroll
    for (int k = 0; k < 16; k++) {
        float lo = W2[(2 * k) * 32 + j];
        float hi = W2[(2 * k + 1) * 32 + j];
        w2sum += lo + hi;
        w2p[k] = pack2(-2.0f * SCL * lo, -2.0f * SCL * hi);
    }
    const u64 b2seed = pack2(SCL * (b2[j] + w2sum), 0.0f);

    // layer-3: r-folded.  ko = L2E*(b3 + SUM W3) + SUM (-2*L2E*W3)*r
    u64 w3p[16];
    float w3sum = 0.0f;
#pragma unroll
    for (int k = 0; k < 16; k++) {
        float lo = W3[(2 * k) * 5 + c];
        float hi = W3[(2 * k + 1) * 5 + c];
        w3sum += lo + hi;
        w3p[k] = pack2(-2.0f * L2E * lo, -2.0f * L2E * hi);
    }
    const u64 b3seed = pack2(L2E * (b3[c] + w3sum), 0.0f);

    // hop-coefficient sets (scaled): half (k2,k3), full (k4), sixth (boundary)
    const float ch0 = 0.5f * w10s, ch1 = 0.5f * w11s;
    const float ch2 = ch1 - ch0, nch1 = -ch1;
    const float cf0 = w10s, cf1 = w11s, cf2 = cf1 - cf0, ncf1 = -cf1;
    const float cs0 = w10s * (1.0f / 6.0f), cs1 = w11s * (1.0f / 6.0f);
    const float cs2 = cs1 - cs0, ncs1 = -cs1;

    // ---- initial state ----
    float s0 = inputs[0];
    float s1 = inputs[1];
    if (j == 0) g_ys[0] = make_float2(s0, s1);

    float p0  = inputs[2];
    float tm0 = inputs[3];
    float ld0 = lday[0];
    float gate_i = fast_step(-tm0);
    float zss    = fmaf(s1, w11s, s0 * w10s);
    float z1s    = fmaf(tm0, w13s, fmaf(p0, w12s, b1js)) + zss;

    float4 fa = g_fc[0];
    float4 fb = g_fc[1];

    const int steps = T - 1;
#pragma unroll 1
    for (int i = 0; i < steps; i++) {
        float4 faN = __ldg(&g_fc[2 * i + 2]);
        float4 fbN = __ldg(&g_fc[2 * i + 3]);

        float ldh = fa.z, gate_h = fa.w;
        float ld1 = fb.z, gate_n = fb.w;

        float a1hs   = fmaf(fa.y, w13s, fmaf(fa.x, w12s, b1js));
        float a1ns   = fmaf(fb.y, w13s, fmaf(fb.x, w12s, b1js));
        float base_h = a1hs + zss;
        float base_n = a1ns + zss;

        // per-step hoisted gate selects (off-path)
        float mA_i = (c == 0) ? 0.5f * gate_i : 0.5f;
        float mA_h = (c == 0) ? 0.5f * gate_h : 0.5f;
        float mA_n = (c == 0) ? 0.5f * gate_n : 0.5f;

        float u0, u1, u2, u3, u4;
        float k1_0, k1_1, k2_0, k2_1, k3_0, k3_1;

        // ---- stage 1 ----
        rhs_eval(c, j, z1s, s0, s1, mA_i, ld0, w2p, b2seed, w3p, b3seed,
                 shA1a, shA2a, u0, u1, u2, u3, u4);
        float z2s = zfromu(u0, u1, u2, u3, u4, base_h, ch0, ch1, ch2, nch1);
        k1_0 = u0 - u2; k1_1 = (u1 + u2) - (u3 + u4);

        // ---- stage 2 ----
        {
            float s0p = fmaf(0.5f, k1_0, s0), s1p = fmaf(0.5f, k1_1, s1);
            rhs_eval(c, j, z2s, s0p, s1p, mA_h, ldh, w2p, b2seed, w3p, b3seed,
                     shB1a, shB2a, u0, u1, u2, u3, u4);
        }
        float z3s = zfromu(u0, u1, u2, u3, u4, base_h, ch0, ch1, ch2, nch1);
        k2_0 = u0 - u2; k2_1 = (u1 + u2) - (u3 + u4);

        // ---- stage 3 ----
        {
            float s0p = fmaf(0.5f, k2_0, s0), s1p = fmaf(0.5f, k2_1, s1);
            rhs_eval(c, j, z3s, s0p, s1p, mA_h, ldh, w2p, b2seed, w3p, b3seed,
                     shA1a, shA2a, u0, u1, u2, u3, u4);
        }
        float z4s = zfromu(u0, u1, u2, u3, u4, base_n, cf0, cf1, cf2, ncf1);
        k3_0 = u0 - u2; k3_1 = (u1 + u2) - (u3 + u4);

        // boundary pre-accumulation (off-path; overlaps stage 4's body)
        float acc0 = k1_0 + 2.0f * (k2_0 + k3_0);
        float acc1 = k1_1 + 2.0f * (k2_1 + k3_1);
        float A    = fmaf(cs1, acc1, fmaf(cs0, acc0, base_n));

        // ---- stage 4 ----
        {
            float s0p = s0 + k3_0, s1p = s1 + k3_1;
            rhs_eval(c, j, z4s, s0p, s1p, mA_n, ld1, w2p, b2seed, w3p, b3seed,
                     shB1a, shB2a, u0, u1, u2, u3, u4);
        }
        // next step's layer-1 preactivation straight from stage-4 u's
        z1s = zfromu(u0, u1, u2, u3, u4, A, cs0, cs1, cs2, ncs1);

        float k4_0 = u0 - u2, k4_1 = (u1 + u2) - (u3 + u4);
        s0 = fmaf(1.0f / 6.0f, acc0 + k4_0, s0);
        s1 = fmaf(1.0f / 6.0f, acc1 + k4_1, s1);
        // zss RE-ANCHORED to exact s every step (no drift)
        zss = fmaf(s1, w11s, s0 * w10s);

        if (j == 0) g_ys[i + 1] = make_float2(s0, s1);

        // rolls
        gate_i = gate_n; ld0 = ld1;
        fa = faN; fb = fbN;
    }
}

// Parallel final MLP over the trajectory: out[t] = mlp(x_t)[4].
__global__ void final_mlp_kernel(const float* __restrict__ inputs,
                                 const float* __restrict__ W1,
                                 const float* __restrict__ b1,
                                 const float* __restrict__ W2,
                                 const float* __restrict__ b2,
                                 const float* __restrict__ W3,
                                 const float* __restrict__ b3,
                                 float* __restrict__ out,
                                 int T)
{
    __shared__ float sW1[128];
    __shared__ float sb1[32];
    __shared__ float sW2[1024];
    __shared__ float sb2[32];
    __shared__ float sW3c[32];

    const int tid = threadIdx.x;
    for (int i = tid; i < 128;  i += blockDim.x) sW1[i] = W1[i];
    for (int i = tid; i < 32;   i += blockDim.x) sb1[i] = b1[i];
    for (int i = tid; i < 1024; i += blockDim.x) sW2[i] = W2[i];
    for (int i = tid; i < 32;   i += blockDim.x) sb2[i] = b2[i];
    for (int i = tid; i < 32;   i += blockDim.x) sW3c[i] = W3[i * 5 + 4];
    __syncthreads();

    const int t = blockIdx.x * blockDim.x + tid;
    if (t >= T) return;

    float2 y = g_ys[t];
    float s0 = fmaxf(y.x, 0.0f);
    float s1 = fmaxf(y.y, 0.0f);
    const float* row = inputs + (size_t)t * 5;
    float p  = row[2];
    float tm = row[3];

    float h1[32];
#pragma unroll
    for (int k = 0; k < 32; k++) {
        float z = sb1[k];
        z = fmaf(s0, sW1[0 * 32 + k], z);
        z = fmaf(s1, sW1[1 * 32 + k], z);
        z = fmaf(p,  sW1[2 * 32 + k], z);
        z = fmaf(tm, sW1[3 * 32 + k], z);
        h1[k] = tanh_scaled(z * SCL);
    }

    float acc = b3[4];
#pragma unroll
    for (int jj = 0; jj < 32; jj++) {
        float a = sb2[jj];
#pragma unroll
        for (int k = 0; k < 32; k++) {
            a = fmaf(h1[k], sW2[k * 32 + jj], a);
        }
        acc = fmaf(tanh_scaled(a * SCL), sW3c[jj], acc);
    }
    out[t] = acc;
}

extern "C" void kernel_launch(void* const* d_in, const int* in_sizes, int n_in,
                              void* d_out, int out_size)
{
    const float* inputs = (const float*)d_in[0];
    const float* lday   = (const float*)d_in[1];
    const float* W1     = (const float*)d_in[2];
    const float* b1     = (const float*)d_in[3];
    const float* W2     = (const float*)d_in[4];
    const float* b2     = (const float*)d_in[5];
    const float* W3     = (const float*)d_in[6];
    const float* b3     = (const float*)d_in[7];

    const int T = in_sizes[1];   // lday has T elements

    forcing_kernel<<<(T + 255) / 256, 256>>>(inputs, lday, T);
    scan_kernel<<<1, 32>>>(inputs, lday, W1, b1, W2, b2, W3, b3, T);

    const int threads = 256;
    const int blocks  = (T + threads - 1) / threads;
    final_mlp_kernel<<<blocks, threads>>>(inputs, W1, b1, W2, b2, W3, b3,
                                          (float*)d_out, T);
}